// round 5
// baseline (speedup 1.0000x reference)
#include <cuda_runtime.h>
#include <cstdint>

#define B_  4
#define S_  2048
#define D_  256
#define NH_ 12

// fp32 scratch for projected QK and V, layout [b][n][f][d]  (100 MB each)
__device__ float g_qk[(size_t)B_ * NH_ * S_ * D_];
__device__ float g_v [(size_t)B_ * NH_ * S_ * D_];

// ---------------- packed f32x2 helpers (Blackwell FFMA2 path) ----------------
__device__ __forceinline__ unsigned long long ffma2(unsigned long long a,
                                                    unsigned long long b,
                                                    unsigned long long c) {
    unsigned long long d;
    asm("fma.rn.f32x2 %0, %1, %2, %3;" : "=l"(d) : "l"(a), "l"(b), "l"(c));
    return d;
}
__device__ __forceinline__ unsigned long long fmul2(unsigned long long a,
                                                    unsigned long long b) {
    unsigned long long d;
    asm("mul.rn.f32x2 %0, %1, %2;" : "=l"(d) : "l"(a), "l"(b));
    return d;
}
__device__ __forceinline__ unsigned long long fpack2(float lo, float hi) {
    unsigned long long d;
    asm("mov.b64 %0, {%1, %2};" : "=l"(d) : "f"(lo), "f"(hi));
    return d;
}
__device__ __forceinline__ float2 funpack2(unsigned long long v) {
    float lo, hi;
    asm("mov.b64 {%0, %1}, %2;" : "=f"(lo), "=f"(hi) : "l"(v));
    return make_float2(lo, hi);
}

// ---------------- projection: [8192,256] x [256,3072] (+bias), x2 ----------------
// grid (24, 64, 2), block 256. Tile 128x128, k-step 8, 8x8 microtile (n-paired FFMA2).
__global__ __launch_bounds__(256, 2)
void proj_kernel(const float* __restrict__ X,
                 const float* __restrict__ Wqk, const float* __restrict__ bqk,
                 const float* __restrict__ Wv,  const float* __restrict__ bvp)
{
    const float* W    = (blockIdx.z == 0) ? Wqk : Wv;
    const float* bias = (blockIdx.z == 0) ? bqk : bvp;
    float* Out        = (blockIdx.z == 0) ? g_qk : g_v;

    __shared__ float As[8][128];   // X chunk transposed: As[k][m]
    __shared__ float Bs[8][128];   // W chunk:            Bs[k][n]

    const int t  = threadIdx.x;
    const int tx = t & 15, ty = t >> 4;
    const int m0 = blockIdx.y * 128;
    const int c0 = blockIdx.x * 128;

    unsigned long long acc[8][4];  // 8 m-rows x 4 n-pairs
#pragma unroll
    for (int i = 0; i < 8; i++)
#pragma unroll
        for (int j = 0; j < 4; j++) acc[i][j] = 0ull;

    const int lm = t >> 1;            // 0..127
    const int lk = (t & 1) * 4;       // 0 or 4
    const int brow = t >> 5;          // 0..7
    const int bcol = (t & 31) * 4;    // 0..124

    for (int k0 = 0; k0 < 256; k0 += 8) {
        float4 xa = *(const float4*)&X[(size_t)(m0 + lm) * 256 + k0 + lk];
        float4 wb = *(const float4*)&W[(size_t)(k0 + brow) * 3072 + c0 + bcol];
        __syncthreads();
        As[lk + 0][lm] = xa.x; As[lk + 1][lm] = xa.y;
        As[lk + 2][lm] = xa.z; As[lk + 3][lm] = xa.w;
        *(float4*)&Bs[brow][bcol] = wb;
        __syncthreads();
#pragma unroll
        for (int kk = 0; kk < 8; kk++) {
            float a[8];
            *(float4*)&a[0] = *(const float4*)&As[kk][ty * 8];
            *(float4*)&a[4] = *(const float4*)&As[kk][ty * 8 + 4];
            ulonglong2 b01 = *(const ulonglong2*)&Bs[kk][tx * 8];
            ulonglong2 b23 = *(const ulonglong2*)&Bs[kk][tx * 8 + 4];
            unsigned long long bp[4] = {b01.x, b01.y, b23.x, b23.y};
#pragma unroll
            for (int i = 0; i < 8; i++) {
                unsigned long long ap = fpack2(a[i], a[i]);
#pragma unroll
                for (int j = 0; j < 4; j++) acc[i][j] = ffma2(ap, bp[j], acc[i][j]);
            }
        }
    }

    // epilogue: add bias, scatter to [b][n][f][d]
#pragma unroll
    for (int j = 0; j < 4; j++) {
        int col = c0 + tx * 8 + 2 * j;           // global column (n*256 + d)
        float2 bb = *(const float2*)&bias[col];
        int nh = col >> 8, d = col & 255;
#pragma unroll
        for (int i = 0; i < 8; i++) {
            int m = m0 + ty * 8 + i;             // global row (b*2048 + f)
            int bb_ = m >> 11, f = m & 2047;
            float2 v = funpack2(acc[i][j]);
            v.x += bb.x; v.y += bb.y;
            *(float2*)&Out[(((size_t)bb_ * NH_ + nh) * S_ + f) * D_ + d] = v;
        }
    }
}

// ---------------- flash attention (fp32, FFMA2), sum over heads via atomics ----------------
// grid (S/64=32, NH=12, B=4), block 256, dynamic smem ~210 KB.
#define QT 64
#define KT 64
#define KPAD 260   // K tile row stride (floats)
#define SPAD 67    // score tile row stride (floats)

__global__ __launch_bounds__(256, 1)
void attn_kernel(const float* __restrict__ X, const int* __restrict__ mask,
                 float* __restrict__ out)
{
    extern __shared__ float sm[];
    float* Qs   = sm;                        // [64][256]
    float* Ks   = Qs + 64 * 256;             // [64][KPAD]
    float* Vs   = Ks + 64 * KPAD;            // [64][256]
    float* Ss   = Vs + 64 * 256;             // [64][SPAD]
    float* m_sm = Ss + 64 * SPAD;            // [64]
    float* l_sm = m_sm + 64;                 // [64]
    float* sc_sm= l_sm + 64;                 // [64]

    const int t  = threadIdx.x;
    const int q0 = blockIdx.x * QT;
    const int nh = blockIdx.y;
    const int bb = blockIdx.z;

    const int tx = t & 15, ty = t >> 4;      // S-phase map: q = ty*4+i, k = tx+16j
    const int dg = t >> 4;                   // O-phase: d-pair group 0..15
    const int lrow = t >> 2, lcs = (t & 3) * 4;  // tile load map

    // load Q tile (= X rows) once
    {
        const float* gQ = X + ((size_t)bb * S_ + q0 + lrow) * D_;
#pragma unroll
        for (int i = 0; i < 16; i++) {
            int c = lcs + 16 * i;
            *(float4*)&Qs[lrow * 256 + c] = *(const float4*)&gQ[c];
        }
    }
    if (t < 64) { m_sm[t] = -3.4e38f; l_sm[t] = 0.0f; }

    unsigned long long o2[4][8];             // O acc: (q=(t&15)+16i, dpair=dg+16j)
#pragma unroll
    for (int i = 0; i < 4; i++)
#pragma unroll
        for (int j = 0; j < 8; j++) o2[i][j] = 0ull;

    const float* gK = g_qk + (size_t)(bb * NH_ + nh) * S_ * D_;
    const float* gV = g_v  + (size_t)(bb * NH_ + nh) * S_ * D_;
    const int*   gM = mask + (size_t)bb * S_ * S_;

    for (int kt = 0; kt < S_ / KT; kt++) {
        const int f0 = kt * KT;
        __syncthreads();   // previous O-phase done before overwriting tiles
        // ---- load K, V tiles ----
        {
            const float* srcK = gK + (size_t)(f0 + lrow) * D_;
            const float* srcV = gV + (size_t)(f0 + lrow) * D_;
#pragma unroll
            for (int i = 0; i < 16; i++) {
                int c = lcs + 16 * i;
                *(float4*)&Ks[lrow * KPAD + c] = *(const float4*)&srcK[c];
                *(float4*)&Vs[lrow * 256  + c] = *(const float4*)&srcV[c];
            }
        }
        __syncthreads();
        // ---- S phase: S[q][k] = Q·K^T (pair over d) ----
        {
            unsigned long long acc[4][4];
#pragma unroll
            for (int i = 0; i < 4; i++)
#pragma unroll
                for (int j = 0; j < 4; j++) acc[i][j] = 0ull;
#pragma unroll 4
            for (int d4 = 0; d4 < 64; d4++) {
                ulonglong2 qv[4], kv[4];
#pragma unroll
                for (int i = 0; i < 4; i++)
                    qv[i] = *(const ulonglong2*)&Qs[(ty * 4 + i) * 256 + 4 * d4];
#pragma unroll
                for (int j = 0; j < 4; j++)
                    kv[j] = *(const ulonglong2*)&Ks[(tx + 16 * j) * KPAD + 4 * d4];
#pragma unroll
                for (int i = 0; i < 4; i++)
#pragma unroll
                    for (int j = 0; j < 4; j++) {
                        acc[i][j] = ffma2(qv[i].x, kv[j].x, acc[i][j]);
                        acc[i][j] = ffma2(qv[i].y, kv[j].y, acc[i][j]);
                    }
            }
#pragma unroll
            for (int i = 0; i < 4; i++) {
                int qrow = ty * 4 + i;
#pragma unroll
                for (int j = 0; j < 4; j++) {
                    int kcol = tx + 16 * j;
                    float2 p = funpack2(acc[i][j]);
                    float s = p.x + p.y;
                    int mv = gM[(size_t)(q0 + qrow) * S_ + f0 + kcol];
                    s += (1.0f - (float)mv) * -10000.0f;
                    Ss[qrow * SPAD + kcol] = s;
                }
            }
        }
        __syncthreads();
        // ---- online softmax over this key tile ----
        {
            const int r = t >> 2, seg = t & 3;   // 4 lanes per row (consecutive)
            float mloc = -3.4e38f;
#pragma unroll
            for (int cc = 0; cc < 16; cc++)
                mloc = fmaxf(mloc, Ss[r * SPAD + seg * 16 + cc]);
            mloc = fmaxf(mloc, __shfl_xor_sync(0xffffffffu, mloc, 1));
            mloc = fmaxf(mloc, __shfl_xor_sync(0xffffffffu, mloc, 2));
            float mold = m_sm[r];
            float mnew = fmaxf(mold, mloc);
            float lsum = 0.0f;
#pragma unroll
            for (int cc = 0; cc < 16; cc++) {
                int c = seg * 16 + cc;
                float p = __expf(Ss[r * SPAD + c] - mnew);
                Ss[r * SPAD + c] = p;
                lsum += p;
            }
            lsum += __shfl_xor_sync(0xffffffffu, lsum, 1);
            lsum += __shfl_xor_sync(0xffffffffu, lsum, 2);
            if (seg == 0) {
                float sc = __expf(mold - mnew);   // exp(-inf)=0 on first tile
                sc_sm[r] = sc;
                l_sm[r]  = l_sm[r] * sc + lsum;
                m_sm[r]  = mnew;
            }
        }
        __syncthreads();
        // ---- O phase: rescale + O += P·V (pair over output d) ----
        {
#pragma unroll
            for (int i = 0; i < 4; i++) {
                float sc = sc_sm[(t & 15) + 16 * i];
                unsigned long long sc2 = fpack2(sc, sc);
#pragma unroll
                for (int j = 0; j < 8; j++) o2[i][j] = fmul2(sc2, o2[i][j]);
            }
#pragma unroll 2
            for (int k = 0; k < KT; k++) {
                unsigned long long p2[4];
#pragma unroll
                for (int i = 0; i < 4; i++) {
                    float p = Ss[((t & 15) + 16 * i) * SPAD + k];
                    p2[i] = fpack2(p, p);
                }
#pragma unroll
                for (int j = 0; j < 8; j++) {
                    unsigned long long v2 =
                        *(const unsigned long long*)&Vs[k * 256 + 2 * (dg + 16 * j)];
#pragma unroll
                    for (int i = 0; i < 4; i++) o2[i][j] = ffma2(p2[i], v2, o2[i][j]);
                }
            }
        }
    }
    __syncthreads();
    // ---- epilogue: divide by l, head-sum into out via float2 atomics ----
#pragma unroll
    for (int i = 0; i < 4; i++) {
        int q = (t & 15) + 16 * i;
        float inv = 1.0f / l_sm[q];
#pragma unroll
        for (int j = 0; j < 8; j++) {
            float2 v = funpack2(o2[i][j]);
            v.x *= inv; v.y *= inv;
            atomicAdd((float2*)&out[((size_t)bb * S_ + q0 + q) * D_ + 2 * (dg + 16 * j)], v);
        }
    }
}

// ---------------- launch ----------------
extern "C" void kernel_launch(void* const* d_in, const int* in_sizes, int n_in,
                              void* d_out, int out_size)
{
    (void)in_sizes; (void)n_in;
    const float* X   = (const float*)d_in[0];
    const int*   msk = (const int*)  d_in[1];
    const float* Wqk = (const float*)d_in[2];
    const float* bqk = (const float*)d_in[3];
    const float* Wv  = (const float*)d_in[4];
    const float* bv  = (const float*)d_in[5];
    float* out = (float*)d_out;

    cudaMemsetAsync(out, 0, (size_t)out_size * sizeof(float), 0);

    dim3 pg(3072 / 128, (B_ * S_) / 128, 2);
    proj_kernel<<<pg, 256>>>(X, Wqk, bqk, Wv, bv);

    const int smem_bytes =
        (64 * 256 + 64 * KPAD + 64 * 256 + 64 * SPAD + 3 * 64) * (int)sizeof(float);
    cudaFuncSetAttribute(attn_kernel,
                         cudaFuncAttributeMaxDynamicSharedMemorySize, smem_bytes);
    dim3 ag(S_ / QT, NH_, B_);
    attn_kernel<<<ag, 256, smem_bytes>>>(X, msk, out);
}